// round 10
// baseline (speedup 1.0000x reference)
#include <cuda_runtime.h>
#include <cuda_fp16.h>
#include <math.h>
#include <stdint.h>

#define BMAX    8192
#define DDIM    128
#define MARGIN  0.5f
#define BM      128
#define BN      128
#define CHUNK   8             // column tiles per CTA
#define THREADS 256

#define ENC_NEGINF 0x007FFFFFu   // enc(-inf)
#define ENC_POSINF 0xFF800000u   // enc(+inf)

// ---------------- device globals -------------------------------------------
__device__ __half g_hi[BMAX * DDIM];
__device__ float g_sqn[BMAX];
__device__ unsigned int g_posE[BMAX];
__device__ unsigned int g_negE[BMAX];

// ---------------- smem byte offsets ----------------------------------------
#define OFF_AHI    0            // 128*256 = 32768
#define OFF_B0     32768
#define OFF_B1     65536
#define OFF_SQALL  98304        // CHUNK*128 floats = 4096B
#define OFF_LBLALL 102400       // CHUNK*128 ints   = 4096B
#define SMEM_SZ    106496       // 104 KB -> 2 CTAs/SM

// ---------------- PTX helpers ----------------------------------------------
__device__ __forceinline__ uint32_t smem_u32(const void* p) {
    uint32_t a;
    asm("{ .reg .u64 t; cvta.to.shared.u64 t, %1; cvt.u32.u64 %0, t; }"
        : "=r"(a) : "l"(p));
    return a;
}
__device__ __forceinline__ void cpa16(uint32_t dst, const void* src) {
    asm volatile("cp.async.cg.shared.global [%0], [%1], 16;"
                 :: "r"(dst), "l"(__cvta_generic_to_global(src)));
}
__device__ __forceinline__ void cpa_commit() {
    asm volatile("cp.async.commit_group;" ::: "memory");
}
template <int N>
__device__ __forceinline__ void cpa_wait() {
    asm volatile("cp.async.wait_group %0;" :: "n"(N) : "memory");
}
__device__ __forceinline__ void ldsm4(uint32_t* r, uint32_t addr) {
    asm volatile("ldmatrix.sync.aligned.m8n8.x4.shared.b16 {%0,%1,%2,%3}, [%4];"
                 : "=r"(r[0]), "=r"(r[1]), "=r"(r[2]), "=r"(r[3]) : "r"(addr));
}
__device__ __forceinline__ void mma_f16(float* c, const uint32_t* a,
                                        const uint32_t* b) {
    asm volatile(
        "mma.sync.aligned.m16n8k16.row.col.f32.f16.f16.f32 "
        "{%0,%1,%2,%3}, {%4,%5,%6,%7}, {%8,%9}, {%0,%1,%2,%3};"
        : "+f"(c[0]), "+f"(c[1]), "+f"(c[2]), "+f"(c[3])
        : "r"(a[0]), "r"(a[1]), "r"(a[2]), "r"(a[3]), "r"(b[0]), "r"(b[1]));
}
__device__ __forceinline__ uint32_t swz(uint32_t base, int row, int c) {
    return base + (uint32_t)(row * 256) + (uint32_t)(((c ^ (row & 7)) << 4));
}
// order-preserving float<->uint encode for atomic max/min
__device__ __forceinline__ unsigned int encf(float f) {
    unsigned int u = __float_as_uint(f);
    return (u & 0x80000000u) ? ~u : (u | 0x80000000u);
}
__device__ __forceinline__ float decf(unsigned int e) {
    unsigned int u = (e & 0x80000000u) ? (e ^ 0x80000000u) : ~e;
    return __uint_as_float(u);
}

// ---------------------------------------------------------------------------
// Kernel 0: fp32 -> fp16 + squared norms (fp32) + result-buffer init.
// ---------------------------------------------------------------------------
__global__ void convert_kernel(const float* __restrict__ emb, int B) {
    int warp = (blockIdx.x * blockDim.x + threadIdx.x) >> 5;
    int lane = threadIdx.x & 31;
    if (warp >= B) return;
    const float4* row = (const float4*)(emb + (size_t)warp * DDIM);
    float4 v = row[lane];
    float s = v.x * v.x + v.y * v.y + v.z * v.z + v.w * v.w;
    #pragma unroll
    for (int off = 16; off; off >>= 1) s += __shfl_xor_sync(0xffffffffu, s, off);
    if (lane == 0) g_sqn[warp] = s;
    if (lane == 1) g_posE[warp] = ENC_NEGINF;
    if (lane == 2) g_negE[warp] = ENC_POSINF;

    __half2* hp = (__half2*)(g_hi + (size_t)warp * DDIM + lane * 4);
    hp[0] = __halves2half2(__float2half_rn(v.x), __float2half_rn(v.y));
    hp[1] = __halves2half2(__float2half_rn(v.z), __float2half_rn(v.w));
}

// ---------------------------------------------------------------------------
// B tile loader (cp.async, swizzled). B data only — metadata is separate.
// ---------------------------------------------------------------------------
__device__ __forceinline__ void load_btile(uint32_t sbase, int which, int c0,
                                           int tid) {
    uint32_t off_b = which ? OFF_B1 : OFF_B0;
    #pragma unroll
    for (int i = 0; i < 8; i++) {
        int chunk = tid + i * THREADS;        // 0..2047
        int row = chunk >> 4;
        int c   = chunk & 15;
        cpa16(swz(sbase + off_b, row, c),
              g_hi + (size_t)(c0 + row) * DDIM + c * 8);
    }
}

// ---------------------------------------------------------------------------
// Kernel 1: upper-triangle fp16 Gram + two-direction batch-hard mining.
// Each CTA: one row block rb, up to CHUNK column tiles cb >= rb. 2 CTAs/SM.
// ---------------------------------------------------------------------------
__global__ __launch_bounds__(THREADS, 2)
void tile_kernel(const int* __restrict__ labels, int B) {
    extern __shared__ char smem[];
    const uint32_t sbase = smem_u32(smem);
    const int tid  = threadIdx.x;
    const int lane = tid & 31;
    const int wid  = tid >> 5;
    const int wm   = wid & 3;
    const int wn   = wid >> 2;
    const int NB   = B / BM;

    // ---- map blockIdx -> (rb, chunk) ----
    int b = blockIdx.x, rb = 0;
    for (;;) {
        int ch = (NB - rb + CHUNK - 1) / CHUNK;
        if (b < ch) break;
        b -= ch; rb++;
    }
    const int cb0 = rb + b * CHUNK;
    const int nt = min(CHUNK, NB - cb0);
    const int r0 = rb * BM;

    float* sq_all  = (float*)(smem + OFF_SQALL);
    int*   lbl_all = (int*)(smem + OFF_LBLALL);

    // ---- prologue: A + B(0) in one group --------------------------------
    #pragma unroll
    for (int i = 0; i < 8; i++) {
        int chunk = tid + i * THREADS;
        int row = chunk >> 4;
        int c   = chunk & 15;
        cpa16(swz(sbase + OFF_AHI, row, c),
              g_hi + (size_t)(r0 + row) * DDIM + c * 8);
    }
    load_btile(sbase, 0, cb0 * BN, tid);
    cpa_commit();

    // all column metadata for this CTA, loaded once (plain loads)
    for (int i = tid; i < nt * BN; i += THREADS) {
        sq_all[i]  = g_sqn[cb0 * BN + i];
        lbl_all[i] = labels[cb0 * BN + i];
    }

    // my 4 anchor rows
    const int g  = lane >> 2;
    const int t4 = lane & 3;
    int rowsG[4]; int labR[4]; float sqR[4];
    #pragma unroll
    for (int s = 0; s < 4; s++) {
        int rl = wm * 32 + (s >> 1) * 16 + (s & 1) * 8 + g;
        rowsG[s] = r0 + rl;
        labR[s]  = labels[r0 + rl];
        sqR[s]   = g_sqn[r0 + rl];
    }

    float pos[4], neg[4];
    #pragma unroll
    for (int s = 0; s < 4; s++) { pos[s] = -INFINITY; neg[s] = INFINITY; }

    const int aRow = (lane & 15);
    const int aCb  = (lane >> 4);
    const int bRow = (lane & 7) + ((lane >> 4) << 3);
    const int bCb  = (lane >> 3) & 1;
    const bool colLane = (((lane >> 2) & 3) == 0);   // g == 0 or g == 4

    // ---- main loop: 1-deep pipeline ------------------------------------
    for (int t = 0; t < nt; t++) {
        cpa_wait<0>();            // tile t resident
        __syncthreads();          // and buffer (t+1)&1 fully drained

        // prefetch t+1 NOW; its latency hides under MMA + epilogue of t
        if (t + 1 < nt) {
            load_btile(sbase, (t + 1) & 1, (cb0 + t + 1) * BN, tid);
            cpa_commit();
        }

        const uint32_t bBase = sbase + ((t & 1) ? OFF_B1 : OFF_B0);
        const float* sq_s  = sq_all + t * BN;
        const int*   lbl_s = lbl_all + t * BN;
        const int cb = cb0 + t;
        const bool diag = (cb == rb);
        const int cg0 = cb * BN;

        float acc[2][8][4];
        #pragma unroll
        for (int mi = 0; mi < 2; mi++)
            #pragma unroll
            for (int ni = 0; ni < 8; ni++)
                #pragma unroll
                for (int q = 0; q < 4; q++) acc[mi][ni][q] = 0.f;

        #pragma unroll
        for (int ks = 0; ks < 8; ks++) {
            uint32_t ahi[2][4], bhi[4][4];
            #pragma unroll
            for (int mi = 0; mi < 2; mi++) {
                int row = wm * 32 + mi * 16 + aRow;
                ldsm4(ahi[mi], swz(sbase + OFF_AHI, row, ks * 2 + aCb));
            }
            #pragma unroll
            for (int nj = 0; nj < 4; nj++) {
                int row = wn * 64 + nj * 16 + bRow;
                ldsm4(bhi[nj], swz(bBase, row, ks * 2 + bCb));
            }
            #pragma unroll
            for (int mi = 0; mi < 2; mi++)
                #pragma unroll
                for (int ni = 0; ni < 8; ni++)
                    mma_f16(acc[mi][ni], ahi[mi], &bhi[ni >> 1][(ni & 1) * 2]);
        }

        // ---- row-direction mining (anchors = this CTA's rows) ----------
        #pragma unroll
        for (int ni = 0; ni < 8; ni++) {
            int colLoc = wn * 64 + ni * 8 + t4 * 2;
            float sq0 = sq_s[colLoc], sq1 = sq_s[colLoc + 1];
            int   l0  = lbl_s[colLoc], l1 = lbl_s[colLoc + 1];
            int   j0  = cg0 + colLoc;
            #pragma unroll
            for (int s = 0; s < 4; s++) {
                float v0 = fmaf(-2.f, acc[s >> 1][ni][(s & 1) * 2], sq0);
                float v1 = fmaf(-2.f, acc[s >> 1][ni][(s & 1) * 2 + 1], sq1);
                if (l0 == labR[s]) {
                    if (j0 != rowsG[s]) pos[s] = fmaxf(pos[s], v0);
                } else neg[s] = fminf(neg[s], v0);
                if (l1 == labR[s]) {
                    if (j0 + 1 != rowsG[s]) pos[s] = fmaxf(pos[s], v1);
                } else neg[s] = fminf(neg[s], v1);
            }
        }

        // ---- column-direction mining: 2-stage shfl + dual-lane REDG ----
        if (!diag) {
            #pragma unroll
            for (int ni = 0; ni < 8; ni++) {
                #pragma unroll
                for (int v = 0; v < 2; v++) {
                    int colLoc = wn * 64 + ni * 8 + t4 * 2 + v;
                    int lj = lbl_s[colLoc];
                    float cp = -INFINITY, cn = INFINITY;
                    #pragma unroll
                    for (int s = 0; s < 4; s++) {
                        float val = fmaf(-2.f, acc[s >> 1][ni][(s & 1) * 2 + v],
                                         sqR[s]);
                        if (labR[s] == lj) cp = fmaxf(cp, val);
                        else               cn = fminf(cn, val);
                    }
                    cp = fmaxf(cp, __shfl_xor_sync(0xffffffffu, cp, 4));
                    cn = fminf(cn, __shfl_xor_sync(0xffffffffu, cn, 4));
                    cp = fmaxf(cp, __shfl_xor_sync(0xffffffffu, cp, 8));
                    cn = fminf(cn, __shfl_xor_sync(0xffffffffu, cn, 8));
                    if (colLane) {      // lanes g=0 and g=4 merge via L2
                        atomicMax(&g_posE[cg0 + colLoc], encf(cp));
                        atomicMin(&g_negE[cg0 + colLoc], encf(cn));
                    }
                }
            }
        }
    }

    // ---- row results: reduce over t4, atomic-merge ----------------------
    #pragma unroll
    for (int s = 0; s < 4; s++) {
        #pragma unroll
        for (int off = 1; off < 4; off <<= 1) {
            pos[s] = fmaxf(pos[s], __shfl_xor_sync(0xffffffffu, pos[s], off));
            neg[s] = fminf(neg[s], __shfl_xor_sync(0xffffffffu, neg[s], off));
        }
    }
    if (t4 == 0) {
        #pragma unroll
        for (int s = 0; s < 4; s++) {
            atomicMax(&g_posE[rowsG[s]], encf(pos[s]));
            atomicMin(&g_negE[rowsG[s]], encf(neg[s]));
        }
    }
}

// ---------------------------------------------------------------------------
// Kernel 2: decode, per-anchor loss, global mean.
// ---------------------------------------------------------------------------
__global__ void finalize_kernel(int B, float* __restrict__ out) {
    __shared__ float ssum[1024];
    __shared__ float scnt[1024];
    int tid = threadIdx.x;
    float sum = 0.f, cnt = 0.f;
    for (int r = tid; r < B; r += 1024) {
        float p = decf(g_posE[r]);
        float n = decf(g_negE[r]);
        bool valid = (p != -INFINITY) && (n != INFINITY);
        float sq = g_sqn[r];
        float hp = sqrtf(fmaxf(sq + p, 0.f));
        float hn = sqrtf(fmaxf(sq + n, 0.f));
        float per = fmaxf(hp - hn + MARGIN, 0.f);
        if (valid) { sum += per; cnt += 1.f; }
    }
    ssum[tid] = sum;
    scnt[tid] = cnt;
    __syncthreads();
    for (int s = 512; s; s >>= 1) {
        if (tid < s) { ssum[tid] += ssum[tid + s]; scnt[tid] += scnt[tid + s]; }
        __syncthreads();
    }
    if (tid == 0) out[0] = ssum[0] / fmaxf(scnt[0], 1.f);
}

// ---------------------------------------------------------------------------
extern "C" void kernel_launch(void* const* d_in, const int* in_sizes, int n_in,
                              void* d_out, int out_size) {
    const float* emb    = (const float*)d_in[0];
    const int*   labels = (const int*)d_in[1];
    const int B = in_sizes[1];                   // 8192
    float* out = (float*)d_out;

    cudaFuncSetAttribute(tile_kernel,
                         cudaFuncAttributeMaxDynamicSharedMemorySize, SMEM_SZ);

    convert_kernel<<<(B * 32 + 255) / 256, 256>>>(emb, B);

    const int NB = B / BM;
    int nCTA = 0;
    for (int rb = 0; rb < NB; rb++) nCTA += (NB - rb + CHUNK - 1) / CHUNK;

    tile_kernel<<<nCTA, THREADS, SMEM_SZ>>>(labels, B);

    finalize_kernel<<<1, 1024>>>(B, out);
}

// round 11
// speedup vs baseline: 1.1019x; 1.1019x over previous
#include <cuda_runtime.h>
#include <cuda_fp16.h>
#include <math.h>
#include <stdint.h>

#define BMAX    8192
#define DDIM    128
#define MARGIN  0.5f
#define BM      128
#define BN      128
#define CHUNK   8             // column tiles per CTA
#define THREADS 256
#define STAGGER_CYC 2048

#define ENC_NEGINF 0x007FFFFFu   // enc(-inf)
#define ENC_POSINF 0xFF800000u   // enc(+inf)

// ---------------- device globals -------------------------------------------
__device__ __half g_hi[BMAX * DDIM];
__device__ float g_sqn[BMAX];
__device__ unsigned int g_posE[BMAX];
__device__ unsigned int g_negE[BMAX];

// ---------------- smem byte offsets ----------------------------------------
#define OFF_AHI    0            // 128*256 = 32768
#define OFF_B0     32768
#define OFF_B1     65536
#define OFF_SQALL  98304        // CHUNK*128 floats = 4096B
#define OFF_LBLALL 102400       // CHUNK*128 ints   = 4096B
#define OFF_COLP   106496       // 4*128 floats = 2048B
#define OFF_COLN   108544
#define SMEM_SZ    110592       // 108 KB -> 2 CTAs/SM

// ---------------- PTX helpers ----------------------------------------------
__device__ __forceinline__ uint32_t smem_u32(const void* p) {
    uint32_t a;
    asm("{ .reg .u64 t; cvta.to.shared.u64 t, %1; cvt.u32.u64 %0, t; }"
        : "=r"(a) : "l"(p));
    return a;
}
__device__ __forceinline__ void cpa16(uint32_t dst, const void* src) {
    asm volatile("cp.async.cg.shared.global [%0], [%1], 16;"
                 :: "r"(dst), "l"(__cvta_generic_to_global(src)));
}
__device__ __forceinline__ void cpa_commit() {
    asm volatile("cp.async.commit_group;" ::: "memory");
}
template <int N>
__device__ __forceinline__ void cpa_wait() {
    asm volatile("cp.async.wait_group %0;" :: "n"(N) : "memory");
}
__device__ __forceinline__ void ldsm4(uint32_t* r, uint32_t addr) {
    asm volatile("ldmatrix.sync.aligned.m8n8.x4.shared.b16 {%0,%1,%2,%3}, [%4];"
                 : "=r"(r[0]), "=r"(r[1]), "=r"(r[2]), "=r"(r[3]) : "r"(addr));
}
__device__ __forceinline__ void mma_f16(float* c, const uint32_t* a,
                                        const uint32_t* b) {
    asm volatile(
        "mma.sync.aligned.m16n8k16.row.col.f32.f16.f16.f32 "
        "{%0,%1,%2,%3}, {%4,%5,%6,%7}, {%8,%9}, {%0,%1,%2,%3};"
        : "+f"(c[0]), "+f"(c[1]), "+f"(c[2]), "+f"(c[3])
        : "r"(a[0]), "r"(a[1]), "r"(a[2]), "r"(a[3]), "r"(b[0]), "r"(b[1]));
}
__device__ __forceinline__ uint32_t swz(uint32_t base, int row, int c) {
    return base + (uint32_t)(row * 256) + (uint32_t)(((c ^ (row & 7)) << 4));
}
// order-preserving float<->uint encode for atomic max/min
__device__ __forceinline__ unsigned int encf(float f) {
    unsigned int u = __float_as_uint(f);
    return (u & 0x80000000u) ? ~u : (u | 0x80000000u);
}
__device__ __forceinline__ float decf(unsigned int e) {
    unsigned int u = (e & 0x80000000u) ? (e ^ 0x80000000u) : ~e;
    return __uint_as_float(u);
}

// ---------------------------------------------------------------------------
// Kernel 0: fp32 -> fp16 + squared norms (fp32) + result-buffer init.
// ---------------------------------------------------------------------------
__global__ void convert_kernel(const float* __restrict__ emb, int B) {
    int warp = (blockIdx.x * blockDim.x + threadIdx.x) >> 5;
    int lane = threadIdx.x & 31;
    if (warp >= B) return;
    const float4* row = (const float4*)(emb + (size_t)warp * DDIM);
    float4 v = row[lane];
    float s = v.x * v.x + v.y * v.y + v.z * v.z + v.w * v.w;
    #pragma unroll
    for (int off = 16; off; off >>= 1) s += __shfl_xor_sync(0xffffffffu, s, off);
    if (lane == 0) g_sqn[warp] = s;
    if (lane == 1) g_posE[warp] = ENC_NEGINF;
    if (lane == 2) g_negE[warp] = ENC_POSINF;

    __half2* hp = (__half2*)(g_hi + (size_t)warp * DDIM + lane * 4);
    hp[0] = __halves2half2(__float2half_rn(v.x), __float2half_rn(v.y));
    hp[1] = __halves2half2(__float2half_rn(v.z), __float2half_rn(v.w));
}

// ---------------------------------------------------------------------------
// B tile loader (cp.async, swizzled). B data only — metadata is separate.
// ---------------------------------------------------------------------------
__device__ __forceinline__ void load_btile(uint32_t sbase, int which, int c0,
                                           int tid) {
    uint32_t off_b = which ? OFF_B1 : OFF_B0;
    #pragma unroll
    for (int i = 0; i < 8; i++) {
        int chunk = tid + i * THREADS;        // 0..2047
        int row = chunk >> 4;
        int c   = chunk & 15;
        cpa16(swz(sbase + off_b, row, c),
              g_hi + (size_t)(c0 + row) * DDIM + c * 8);
    }
}

// ---------------------------------------------------------------------------
// Kernel 1: upper-triangle fp16 Gram + two-direction batch-hard mining.
// Each CTA: one row block rb, up to CHUNK column tiles cb >= rb. 2 CTAs/SM,
// phase-staggered so one CTA's epilogue overlaps the other's MMA.
// ---------------------------------------------------------------------------
__global__ __launch_bounds__(THREADS, 2)
void tile_kernel(const int* __restrict__ labels, int B) {
    extern __shared__ char smem[];
    const uint32_t sbase = smem_u32(smem);
    const int tid  = threadIdx.x;
    const int lane = tid & 31;
    const int wid  = tid >> 5;
    const int wm   = wid & 3;
    const int wn   = wid >> 2;
    const int NB   = B / BM;

    // ---- map blockIdx -> (rb, chunk) ----
    int b = blockIdx.x, rb = 0;
    for (;;) {
        int ch = (NB - rb + CHUNK - 1) / CHUNK;
        if (b < ch) break;
        b -= ch; rb++;
    }
    const int cb0 = rb + b * CHUNK;
    const int nt = min(CHUNK, NB - cb0);
    const int r0 = rb * BM;

    float* sq_all  = (float*)(smem + OFF_SQALL);
    int*   lbl_all = (int*)(smem + OFF_LBLALL);
    float* colP = (float*)(smem + OFF_COLP);
    float* colN = (float*)(smem + OFF_COLN);

    // ---- prologue: A + B(0) in group0, B(1) in group1 ------------------
    #pragma unroll
    for (int i = 0; i < 8; i++) {
        int chunk = tid + i * THREADS;
        int row = chunk >> 4;
        int c   = chunk & 15;
        cpa16(swz(sbase + OFF_AHI, row, c),
              g_hi + (size_t)(r0 + row) * DDIM + c * 8);
    }
    load_btile(sbase, 0, cb0 * BN, tid);
    cpa_commit();                              // group 0
    if (nt > 1) load_btile(sbase, 1, (cb0 + 1) * BN, tid);
    cpa_commit();                              // group 1 (may be empty)

    // all column metadata for this CTA, loaded once
    for (int i = tid; i < nt * BN; i += THREADS) {
        sq_all[i]  = g_sqn[cb0 * BN + i];
        lbl_all[i] = labels[cb0 * BN + i];
    }

    // my 4 anchor rows
    const int g  = lane >> 2;
    const int t4 = lane & 3;
    int rowsG[4]; int labR[4]; float sqR[4];
    #pragma unroll
    for (int s = 0; s < 4; s++) {
        int rl = wm * 32 + (s >> 1) * 16 + (s & 1) * 8 + g;
        rowsG[s] = r0 + rl;
        labR[s]  = labels[r0 + rl];
        sqR[s]   = g_sqn[r0 + rl];
    }

    // ---- anti-phase stagger: the second co-resident CTA (blockIdx>=148)
    // delays half an MMA phase so the two CTAs' MMA/epilogue interleave.
    // Loads above are already in flight; result is timing-only.
    if (blockIdx.x >= 148) {
        long long s0 = clock64();
        while (clock64() - s0 < STAGGER_CYC) { }
    }

    float pos[4], neg[4];
    #pragma unroll
    for (int s = 0; s < 4; s++) { pos[s] = -INFINITY; neg[s] = INFINITY; }

    const int aRow = (lane & 15);
    const int aCb  = (lane >> 4);
    const int bRow = (lane & 7) + ((lane >> 4) << 3);
    const int bCb  = (lane >> 3) & 1;

    // ---- main loop: 2 barriers per tile ---------------------------------
    for (int t = 0; t < nt; t++) {
        cpa_wait<1>();
        __syncthreads();

        const int which = t & 1;
        const uint32_t bBase = sbase + (which ? OFF_B1 : OFF_B0);
        const float* sq_s  = sq_all + t * BN;
        const int*   lbl_s = lbl_all + t * BN;
        const int cb = cb0 + t;
        const bool diag = (cb == rb);
        const int cg0 = cb * BN;

        float acc[2][8][4];
        #pragma unroll
        for (int mi = 0; mi < 2; mi++)
            #pragma unroll
            for (int ni = 0; ni < 8; ni++)
                #pragma unroll
                for (int q = 0; q < 4; q++) acc[mi][ni][q] = 0.f;

        #pragma unroll
        for (int ks = 0; ks < 8; ks++) {
            uint32_t ahi[2][4], bhi[4][4];
            #pragma unroll
            for (int mi = 0; mi < 2; mi++) {
                int row = wm * 32 + mi * 16 + aRow;
                ldsm4(ahi[mi], swz(sbase + OFF_AHI, row, ks * 2 + aCb));
            }
            #pragma unroll
            for (int nj = 0; nj < 4; nj++) {
                int row = wn * 64 + nj * 16 + bRow;
                ldsm4(bhi[nj], swz(bBase, row, ks * 2 + bCb));
            }
            #pragma unroll
            for (int mi = 0; mi < 2; mi++)
                #pragma unroll
                for (int ni = 0; ni < 8; ni++)
                    mma_f16(acc[mi][ni], ahi[mi], &bhi[ni >> 1][(ni & 1) * 2]);
        }

        // ---- row-direction mining (anchors = this CTA's rows) ----------
        #pragma unroll
        for (int ni = 0; ni < 8; ni++) {
            int colLoc = wn * 64 + ni * 8 + t4 * 2;
            float sq0 = sq_s[colLoc], sq1 = sq_s[colLoc + 1];
            int   l0  = lbl_s[colLoc], l1 = lbl_s[colLoc + 1];
            int   j0  = cg0 + colLoc;
            #pragma unroll
            for (int s = 0; s < 4; s++) {
                float v0 = fmaf(-2.f, acc[s >> 1][ni][(s & 1) * 2], sq0);
                float v1 = fmaf(-2.f, acc[s >> 1][ni][(s & 1) * 2 + 1], sq1);
                if (l0 == labR[s]) {
                    if (j0 != rowsG[s]) pos[s] = fmaxf(pos[s], v0);
                } else neg[s] = fminf(neg[s], v0);
                if (l1 == labR[s]) {
                    if (j0 + 1 != rowsG[s]) pos[s] = fmaxf(pos[s], v1);
                } else neg[s] = fminf(neg[s], v1);
            }
        }

        // ---- column-direction partials (anchors = col block) -----------
        if (!diag) {
            #pragma unroll
            for (int ni = 0; ni < 8; ni++) {
                #pragma unroll
                for (int v = 0; v < 2; v++) {
                    int colLoc = wn * 64 + ni * 8 + t4 * 2 + v;
                    int lj = lbl_s[colLoc];
                    float cp = -INFINITY, cn = INFINITY;
                    #pragma unroll
                    for (int s = 0; s < 4; s++) {
                        float val = fmaf(-2.f, acc[s >> 1][ni][(s & 1) * 2 + v],
                                         sqR[s]);
                        if (labR[s] == lj) cp = fmaxf(cp, val);
                        else               cn = fminf(cn, val);
                    }
                    #pragma unroll
                    for (int off = 4; off <= 16; off <<= 1) {
                        cp = fmaxf(cp, __shfl_xor_sync(0xffffffffu, cp, off));
                        cn = fminf(cn, __shfl_xor_sync(0xffffffffu, cn, off));
                    }
                    if (lane < 4) {             // g == 0 lanes
                        colP[wm * 128 + colLoc] = cp;
                        colN[wm * 128 + colLoc] = cn;
                    }
                }
            }
        }

        // single merged barrier: drains B-buffer reads AND colP/colN writes
        __syncthreads();

        // prefetch t+2 into the just-freed buffer; latency hides under the
        // combine/atomics below and the next tile's front.
        if (t + 2 < nt)
            load_btile(sbase, which, (cb0 + t + 2) * BN, tid);
        cpa_commit();   // uniform group counting

        if (!diag) {
            if (tid < 128) {
                float p = colP[tid];
                #pragma unroll
                for (int w = 1; w < 4; w++) p = fmaxf(p, colP[w * 128 + tid]);
                atomicMax(&g_posE[cg0 + tid], encf(p));
            } else {
                int c = tid - 128;
                float n = colN[c];
                #pragma unroll
                for (int w = 1; w < 4; w++) n = fminf(n, colN[w * 128 + c]);
                atomicMin(&g_negE[cg0 + c], encf(n));
            }
        }
    }

    // ---- row results: reduce over t4, atomic-merge ----------------------
    #pragma unroll
    for (int s = 0; s < 4; s++) {
        #pragma unroll
        for (int off = 1; off < 4; off <<= 1) {
            pos[s] = fmaxf(pos[s], __shfl_xor_sync(0xffffffffu, pos[s], off));
            neg[s] = fminf(neg[s], __shfl_xor_sync(0xffffffffu, neg[s], off));
        }
    }
    if (t4 == 0) {
        #pragma unroll
        for (int s = 0; s < 4; s++) {
            atomicMax(&g_posE[rowsG[s]], encf(pos[s]));
            atomicMin(&g_negE[rowsG[s]], encf(neg[s]));
        }
    }
}

// ---------------------------------------------------------------------------
// Kernel 2: decode, per-anchor loss, global mean.
// ---------------------------------------------------------------------------
__global__ void finalize_kernel(int B, float* __restrict__ out) {
    __shared__ float ssum[1024];
    __shared__ float scnt[1024];
    int tid = threadIdx.x;
    float sum = 0.f, cnt = 0.f;
    for (int r = tid; r < B; r += 1024) {
        float p = decf(g_posE[r]);
        float n = decf(g_negE[r]);
        bool valid = (p != -INFINITY) && (n != INFINITY);
        float sq = g_sqn[r];
        float hp = sqrtf(fmaxf(sq + p, 0.f));
        float hn = sqrtf(fmaxf(sq + n, 0.f));
        float per = fmaxf(hp - hn + MARGIN, 0.f);
        if (valid) { sum += per; cnt += 1.f; }
    }
    ssum[tid] = sum;
    scnt[tid] = cnt;
    __syncthreads();
    for (int s = 512; s; s >>= 1) {
        if (tid < s) { ssum[tid] += ssum[tid + s]; scnt[tid] += scnt[tid + s]; }
        __syncthreads();
    }
    if (tid == 0) out[0] = ssum[0] / fmaxf(scnt[0], 1.f);
}

// ---------------------------------------------------------------------------
extern "C" void kernel_launch(void* const* d_in, const int* in_sizes, int n_in,
                              void* d_out, int out_size) {
    const float* emb    = (const float*)d_in[0];
    const int*   labels = (const int*)d_in[1];
    const int B = in_sizes[1];                   // 8192
    float* out = (float*)d_out;

    cudaFuncSetAttribute(tile_kernel,
                         cudaFuncAttributeMaxDynamicSharedMemorySize, SMEM_SZ);

    convert_kernel<<<(B * 32 + 255) / 256, 256>>>(emb, B);

    const int NB = B / BM;
    int nCTA = 0;
    for (int rb = 0; rb < NB; rb++) nCTA += (NB - rb + CHUNK - 1) / CHUNK;

    tile_kernel<<<nCTA, THREADS, SMEM_SZ>>>(labels, B);

    finalize_kernel<<<1, 1024>>>(B, out);
}

// round 12
// speedup vs baseline: 1.2129x; 1.1007x over previous
#include <cuda_runtime.h>
#include <cuda_fp16.h>
#include <math.h>
#include <stdint.h>

#define BMAX    8192
#define DDIM    128
#define MARGIN  0.5f
#define BM      128
#define BN      128
#define CHUNK   8             // column tiles per CTA
#define THREADS 256

#define ENC_NEGINF 0x007FFFFFu   // enc(-inf)
#define ENC_POSINF 0xFF800000u   // enc(+inf)

// ---------------- device globals -------------------------------------------
__device__ __half g_hi[BMAX * DDIM];
__device__ float g_sqn[BMAX];
__device__ unsigned int g_posE[BMAX];
__device__ unsigned int g_negE[BMAX];

// ---------------- smem byte offsets ----------------------------------------
#define OFF_AHI    0            // 128*256 = 32768
#define OFF_B0     32768
#define OFF_B1     65536
#define OFF_SQALL  98304        // CHUNK*128 floats = 4096B
#define OFF_LBLALL 102400       // CHUNK*128 ints   = 4096B
#define OFF_COLP   106496       // 4*128 floats = 2048B
#define OFF_COLN   108544
#define SMEM_SZ    110592       // 108 KB -> 2 CTAs/SM

// ---------------- PTX helpers ----------------------------------------------
__device__ __forceinline__ uint32_t smem_u32(const void* p) {
    uint32_t a;
    asm("{ .reg .u64 t; cvta.to.shared.u64 t, %1; cvt.u32.u64 %0, t; }"
        : "=r"(a) : "l"(p));
    return a;
}
__device__ __forceinline__ void cpa16(uint32_t dst, const void* src) {
    asm volatile("cp.async.cg.shared.global [%0], [%1], 16;"
                 :: "r"(dst), "l"(__cvta_generic_to_global(src)));
}
__device__ __forceinline__ void cpa_commit() {
    asm volatile("cp.async.commit_group;" ::: "memory");
}
template <int N>
__device__ __forceinline__ void cpa_wait() {
    asm volatile("cp.async.wait_group %0;" :: "n"(N) : "memory");
}
__device__ __forceinline__ void ldsm4(uint32_t* r, uint32_t addr) {
    asm volatile("ldmatrix.sync.aligned.m8n8.x4.shared.b16 {%0,%1,%2,%3}, [%4];"
                 : "=r"(r[0]), "=r"(r[1]), "=r"(r[2]), "=r"(r[3]) : "r"(addr));
}
__device__ __forceinline__ void mma_f16(float* c, const uint32_t* a,
                                        const uint32_t* b) {
    asm volatile(
        "mma.sync.aligned.m16n8k16.row.col.f32.f16.f16.f32 "
        "{%0,%1,%2,%3}, {%4,%5,%6,%7}, {%8,%9}, {%0,%1,%2,%3};"
        : "+f"(c[0]), "+f"(c[1]), "+f"(c[2]), "+f"(c[3])
        : "r"(a[0]), "r"(a[1]), "r"(a[2]), "r"(a[3]), "r"(b[0]), "r"(b[1]));
}
__device__ __forceinline__ uint32_t swz(uint32_t base, int row, int c) {
    return base + (uint32_t)(row * 256) + (uint32_t)(((c ^ (row & 7)) << 4));
}
// order-preserving float<->uint encode for atomic max/min
__device__ __forceinline__ unsigned int encf(float f) {
    unsigned int u = __float_as_uint(f);
    return (u & 0x80000000u) ? ~u : (u | 0x80000000u);
}
__device__ __forceinline__ float decf(unsigned int e) {
    unsigned int u = (e & 0x80000000u) ? (e ^ 0x80000000u) : ~e;
    return __uint_as_float(u);
}

// ---------------------------------------------------------------------------
// Kernel 0: fp32 -> fp16 + squared norms (fp32) + result-buffer init.
// ---------------------------------------------------------------------------
__global__ void convert_kernel(const float* __restrict__ emb, int B) {
    int warp = (blockIdx.x * blockDim.x + threadIdx.x) >> 5;
    int lane = threadIdx.x & 31;
    if (warp >= B) return;
    const float4* row = (const float4*)(emb + (size_t)warp * DDIM);
    float4 v = row[lane];
    float s = v.x * v.x + v.y * v.y + v.z * v.z + v.w * v.w;
    #pragma unroll
    for (int off = 16; off; off >>= 1) s += __shfl_xor_sync(0xffffffffu, s, off);
    if (lane == 0) g_sqn[warp] = s;
    if (lane == 1) g_posE[warp] = ENC_NEGINF;
    if (lane == 2) g_negE[warp] = ENC_POSINF;

    __half2* hp = (__half2*)(g_hi + (size_t)warp * DDIM + lane * 4);
    hp[0] = __halves2half2(__float2half_rn(v.x), __float2half_rn(v.y));
    hp[1] = __halves2half2(__float2half_rn(v.z), __float2half_rn(v.w));
}

// ---------------------------------------------------------------------------
// B tile loader (cp.async, swizzled). B data only — metadata is separate.
// ---------------------------------------------------------------------------
__device__ __forceinline__ void load_btile(uint32_t sbase, int which, int c0,
                                           int tid) {
    uint32_t off_b = which ? OFF_B1 : OFF_B0;
    #pragma unroll
    for (int i = 0; i < 8; i++) {
        int chunk = tid + i * THREADS;        // 0..2047
        int row = chunk >> 4;
        int c   = chunk & 15;
        cpa16(swz(sbase + off_b, row, c),
              g_hi + (size_t)(c0 + row) * DDIM + c * 8);
    }
}

// ---------------------------------------------------------------------------
// Kernel 1: upper-triangle fp16 Gram + two-direction batch-hard mining.
// Each CTA: one row block rb, up to CHUNK column tiles cb >= rb. 2 CTAs/SM.
// ---------------------------------------------------------------------------
__global__ __launch_bounds__(THREADS, 2)
void tile_kernel(const int* __restrict__ labels, int B) {
    extern __shared__ char smem[];
    const uint32_t sbase = smem_u32(smem);
    const int tid  = threadIdx.x;
    const int lane = tid & 31;
    const int wid  = tid >> 5;
    const int wm   = wid & 3;
    const int wn   = wid >> 2;
    const int NB   = B / BM;

    // ---- map blockIdx -> (rb, chunk) ----
    int b = blockIdx.x, rb = 0;
    for (;;) {
        int ch = (NB - rb + CHUNK - 1) / CHUNK;
        if (b < ch) break;
        b -= ch; rb++;
    }
    const int cb0 = rb + b * CHUNK;
    const int nt = min(CHUNK, NB - cb0);
    const int r0 = rb * BM;

    float* sq_all  = (float*)(smem + OFF_SQALL);
    int*   lbl_all = (int*)(smem + OFF_LBLALL);
    float* colP = (float*)(smem + OFF_COLP);
    float* colN = (float*)(smem + OFF_COLN);

    // ---- prologue: A + B(0) in group0, B(1) in group1 ------------------
    #pragma unroll
    for (int i = 0; i < 8; i++) {
        int chunk = tid + i * THREADS;
        int row = chunk >> 4;
        int c   = chunk & 15;
        cpa16(swz(sbase + OFF_AHI, row, c),
              g_hi + (size_t)(r0 + row) * DDIM + c * 8);
    }
    load_btile(sbase, 0, cb0 * BN, tid);
    cpa_commit();                              // group 0
    if (nt > 1) load_btile(sbase, 1, (cb0 + 1) * BN, tid);
    cpa_commit();                              // group 1 (may be empty)

    // all column metadata for this CTA, loaded once
    for (int i = tid; i < nt * BN; i += THREADS) {
        sq_all[i]  = g_sqn[cb0 * BN + i];
        lbl_all[i] = labels[cb0 * BN + i];
    }

    // my 4 anchor rows
    const int g  = lane >> 2;
    const int t4 = lane & 3;
    int rowsG[4]; int labR[4]; float sqR[4];
    #pragma unroll
    for (int s = 0; s < 4; s++) {
        int rl = wm * 32 + (s >> 1) * 16 + (s & 1) * 8 + g;
        rowsG[s] = r0 + rl;
        labR[s]  = labels[r0 + rl];
        sqR[s]   = g_sqn[r0 + rl];
    }

    float pos[4], neg[4];
    #pragma unroll
    for (int s = 0; s < 4; s++) { pos[s] = -INFINITY; neg[s] = INFINITY; }

    const int aRow = (lane & 15);
    const int aCb  = (lane >> 4);
    const int bRow = (lane & 7) + ((lane >> 4) << 3);
    const int bCb  = (lane >> 3) & 1;

    // ---- main loop ------------------------------------------------------
    for (int t = 0; t < nt; t++) {
        cpa_wait<1>();
        __syncthreads();

        const int which = t & 1;
        const uint32_t bBase = sbase + (which ? OFF_B1 : OFF_B0);
        const float* sq_s  = sq_all + t * BN;
        const int*   lbl_s = lbl_all + t * BN;
        const int cb = cb0 + t;
        const bool diag = (cb == rb);
        const int cg0 = cb * BN;

        float acc[2][8][4];
        #pragma unroll
        for (int mi = 0; mi < 2; mi++)
            #pragma unroll
            for (int ni = 0; ni < 8; ni++)
                #pragma unroll
                for (int q = 0; q < 4; q++) acc[mi][ni][q] = 0.f;

        #pragma unroll
        for (int ks = 0; ks < 8; ks++) {
            uint32_t ahi[2][4], bhi[4][4];
            #pragma unroll
            for (int mi = 0; mi < 2; mi++) {
                int row = wm * 32 + mi * 16 + aRow;
                ldsm4(ahi[mi], swz(sbase + OFF_AHI, row, ks * 2 + aCb));
            }
            #pragma unroll
            for (int nj = 0; nj < 4; nj++) {
                int row = wn * 64 + nj * 16 + bRow;
                ldsm4(bhi[nj], swz(bBase, row, ks * 2 + bCb));
            }
            #pragma unroll
            for (int mi = 0; mi < 2; mi++)
                #pragma unroll
                for (int ni = 0; ni < 8; ni++)
                    mma_f16(acc[mi][ni], ahi[mi], &bhi[ni >> 1][(ni & 1) * 2]);
        }

        // B buffer `which` consumed; prefetch t+2 before the epilogue so
        // the cp.async latency overlaps mining.
        __syncthreads();
        if (t + 2 < nt)
            load_btile(sbase, which, (cb0 + t + 2) * BN, tid);
        cpa_commit();   // uniform group counting

        if (diag) {
            // ---- diagonal tile: row mining only, with self-exclusion ---
            #pragma unroll
            for (int ni = 0; ni < 8; ni++) {
                int colLoc = wn * 64 + ni * 8 + t4 * 2;
                float sq0 = sq_s[colLoc], sq1 = sq_s[colLoc + 1];
                int   l0  = lbl_s[colLoc], l1 = lbl_s[colLoc + 1];
                int   j0  = cg0 + colLoc;
                #pragma unroll
                for (int s = 0; s < 4; s++) {
                    float v0 = fmaf(-2.f, acc[s >> 1][ni][(s & 1) * 2], sq0);
                    float v1 = fmaf(-2.f, acc[s >> 1][ni][(s & 1) * 2 + 1], sq1);
                    if (l0 == labR[s]) {
                        if (j0 != rowsG[s]) pos[s] = fmaxf(pos[s], v0);
                    } else neg[s] = fminf(neg[s], v0);
                    if (l1 == labR[s]) {
                        if (j0 + 1 != rowsG[s]) pos[s] = fmaxf(pos[s], v1);
                    } else neg[s] = fminf(neg[s], v1);
                }
            }
        } else {
            // ---- off-diagonal: merged row+col mining, shared predicate,
            //      no self-pair possible (row block != col block).
            #pragma unroll
            for (int ni = 0; ni < 8; ni++) {
                #pragma unroll
                for (int v = 0; v < 2; v++) {
                    int colLoc = wn * 64 + ni * 8 + t4 * 2 + v;
                    float sqj = sq_s[colLoc];
                    int   lj  = lbl_s[colLoc];
                    float cp = -INFINITY, cn = INFINITY;
                    #pragma unroll
                    for (int s = 0; s < 4; s++) {
                        // d = -2*acc is exact (x2 scaling), so d+sq rounds
                        // once: bit-identical to fmaf(-2,acc,sq).
                        float d = -2.f * acc[s >> 1][ni][(s & 1) * 2 + v];
                        float vrow = d + sqj;
                        float vcol = d + sqR[s];
                        if (lj == labR[s]) {
                            pos[s] = fmaxf(pos[s], vrow);
                            cp = fmaxf(cp, vcol);
                        } else {
                            neg[s] = fminf(neg[s], vrow);
                            cn = fminf(cn, vcol);
                        }
                    }
                    #pragma unroll
                    for (int off = 4; off <= 16; off <<= 1) {
                        cp = fmaxf(cp, __shfl_xor_sync(0xffffffffu, cp, off));
                        cn = fminf(cn, __shfl_xor_sync(0xffffffffu, cn, off));
                    }
                    if (lane < 4) {             // g == 0 lanes
                        colP[wm * 128 + colLoc] = cp;
                        colN[wm * 128 + colLoc] = cn;
                    }
                }
            }
            __syncthreads();
            if (tid < 128) {
                float p = colP[tid];
                #pragma unroll
                for (int w = 1; w < 4; w++) p = fmaxf(p, colP[w * 128 + tid]);
                atomicMax(&g_posE[cg0 + tid], encf(p));
            } else {
                int c = tid - 128;
                float n = colN[c];
                #pragma unroll
                for (int w = 1; w < 4; w++) n = fminf(n, colN[w * 128 + c]);
                atomicMin(&g_negE[cg0 + c], encf(n));
            }
        }
    }

    // ---- row results: reduce over t4, atomic-merge ----------------------
    #pragma unroll
    for (int s = 0; s < 4; s++) {
        #pragma unroll
        for (int off = 1; off < 4; off <<= 1) {
            pos[s] = fmaxf(pos[s], __shfl_xor_sync(0xffffffffu, pos[s], off));
            neg[s] = fminf(neg[s], __shfl_xor_sync(0xffffffffu, neg[s], off));
        }
    }
    if (t4 == 0) {
        #pragma unroll
        for (int s = 0; s < 4; s++) {
            atomicMax(&g_posE[rowsG[s]], encf(pos[s]));
            atomicMin(&g_negE[rowsG[s]], encf(neg[s]));
        }
    }
}

// ---------------------------------------------------------------------------
// Kernel 2: decode, per-anchor loss, global mean.
// ---------------------------------------------------------------------------
__global__ void finalize_kernel(int B, float* __restrict__ out) {
    __shared__ float ssum[1024];
    __shared__ float scnt[1024];
    int tid = threadIdx.x;
    float sum = 0.f, cnt = 0.f;
    for (int r = tid; r < B; r += 1024) {
        float p = decf(g_posE[r]);
        float n = decf(g_negE[r]);
        bool valid = (p != -INFINITY) && (n != INFINITY);
        float sq = g_sqn[r];
        float hp = sqrtf(fmaxf(sq + p, 0.f));
        float hn = sqrtf(fmaxf(sq + n, 0.f));
        float per = fmaxf(hp - hn + MARGIN, 0.f);
        if (valid) { sum += per; cnt += 1.f; }
    }
    ssum[tid] = sum;
    scnt[tid] = cnt;
    __syncthreads();
    for (int s = 512; s; s >>= 1) {
        if (tid < s) { ssum[tid] += ssum[tid + s]; scnt[tid] += scnt[tid + s]; }
        __syncthreads();
    }
    if (tid == 0) out[0] = ssum[0] / fmaxf(scnt[0], 1.f);
}

// ---------------------------------------------------------------------------
extern "C" void kernel_launch(void* const* d_in, const int* in_sizes, int n_in,
                              void* d_out, int out_size) {
    const float* emb    = (const float*)d_in[0];
    const int*   labels = (const int*)d_in[1];
    const int B = in_sizes[1];                   // 8192
    float* out = (float*)d_out;

    cudaFuncSetAttribute(tile_kernel,
                         cudaFuncAttributeMaxDynamicSharedMemorySize, SMEM_SZ);

    convert_kernel<<<(B * 32 + 255) / 256, 256>>>(emb, B);

    const int NB = B / BM;
    int nCTA = 0;
    for (int rb = 0; rb < NB; rb++) nCTA += (NB - rb + CHUNK - 1) / CHUNK;

    tile_kernel<<<nCTA, THREADS, SMEM_SZ>>>(labels, B);

    finalize_kernel<<<1, 1024>>>(B, out);
}